// round 5
// baseline (speedup 1.0000x reference)
#include <cuda_runtime.h>

typedef unsigned long long u64;
typedef unsigned int u32;

#define TT   64
#define BSS  64
#define DIMM 1024
#define G4   4096
#define SRCN 512

// ---------------- scratch (static device globals; no runtime alloc) ----------
__device__ float g_X [TT*BSS*G4];     // 64 MB: pre-activations X[t,b,4096]
__device__ float g_H [TT*BSS*DIMM];   // 16 MB: hidden history H[t,b,1024]
__device__ float g_Q [TT*BSS*DIMM];   // 16 MB: encoder queries
__device__ float g_QD[TT*BSS*DIMM];   // 16 MB: decoder queries
__device__ float g_E [BSS*TT*SRCN];   //  8 MB: enc scores -> sc -> alpha (in place)
__device__ float g_ED[BSS*TT*TT];     //  1 MB: dec scores -> alpha (in place)
__device__ float g_c [BSS*DIMM];      // cell state

// ---------------- f32x2 packed helpers --------------------------------------
__device__ __forceinline__ void fma2(u64& a, u64 x, u64 y){
    asm("fma.rn.f32x2 %0, %1, %2, %0;" : "+l"(a) : "l"(x), "l"(y));
}
__device__ __forceinline__ u64 dup2(float f){
    u32 u = __float_as_uint(f);
    u64 r; asm("mov.b64 %0, {%1, %1};" : "=l"(r) : "r"(u));
    return r;
}
__device__ __forceinline__ float lo32(u64 v){ return __uint_as_float((u32)v); }
__device__ __forceinline__ float hi32(u64 v){ return __uint_as_float((u32)(v>>32)); }

// ---------------- generic 64x64 NT/NN GEMM, C[m,n] = sum_k A[m,k]*B[.,k] ----
// NT: B[n,k] row-major over n (ldb = stride between n rows)
// NN: B[k,n] row-major over k (ldb = stride between k rows, n contiguous)
// Optional row gather on A (embedding lookup), optional two biases per n.
template<bool GATHER, bool BNN>
__global__ void __launch_bounds__(256) gemm64(
    const float* __restrict__ A, long lda, const int* __restrict__ ridx,
    const float* __restrict__ B, long ldb,
    float* __restrict__ C, long ldc, int K,
    const float* __restrict__ bias1, const float* __restrict__ bias2,
    long bsA, long bsB, long bsC)
{
    __shared__ float At[16][68];
    __shared__ float Bt[16][68];
    const int tid = threadIdx.x;
    const int tx = tid & 15, ty = tid >> 4;
    const int m0 = blockIdx.y * 64;
    const int n0 = blockIdx.x * 64;
    const long z = blockIdx.z;

    const int arow = tid >> 2, akq = tid & 3;
    const float* Arow;
    {
        const float* Ab = A + z * bsA;
        long mrow = m0 + arow;
        if (GATHER) mrow = ridx[mrow];
        Arow = Ab + mrow * lda + akq * 4;
    }
    const float* Brow;
    int bk = 0, bnq = 0, brow = 0, bkq = 0;
    {
        const float* Bb = B + z * bsB;
        if (BNN) { bk = tid >> 4; bnq = tid & 15; Brow = Bb + (long)bk * ldb + n0 + bnq * 4; }
        else     { brow = tid >> 2; bkq = tid & 3; Brow = Bb + (long)(n0 + brow) * ldb + bkq * 4; }
    }

    u64 acc[2][4];
    #pragma unroll
    for (int p = 0; p < 2; p++)
        #pragma unroll
        for (int j = 0; j < 4; j++) acc[p][j] = 0ull;

    float4 ra = *(const float4*)(Arow);
    float4 rb = *(const float4*)(Brow);

    for (int k0 = 0; k0 < K; k0 += 16) {
        __syncthreads();
        At[akq*4+0][arow] = ra.x;
        At[akq*4+1][arow] = ra.y;
        At[akq*4+2][arow] = ra.z;
        At[akq*4+3][arow] = ra.w;
        if (BNN) {
            *(float4*)&Bt[bk][bnq*4] = rb;
        } else {
            Bt[bkq*4+0][brow] = rb.x;
            Bt[bkq*4+1][brow] = rb.y;
            Bt[bkq*4+2][brow] = rb.z;
            Bt[bkq*4+3][brow] = rb.w;
        }
        __syncthreads();
        if (k0 + 16 < K) {
            ra = *(const float4*)(Arow + k0 + 16);
            rb = BNN ? *(const float4*)(Brow + (long)(k0 + 16) * ldb)
                     : *(const float4*)(Brow + k0 + 16);
        }
        #pragma unroll
        for (int k = 0; k < 16; k++) {
            u64 a01 = *(const u64*)&At[k][ty*4];
            u64 a23 = *(const u64*)&At[k][ty*4+2];
            float4 bv = *(const float4*)&Bt[k][tx*4];
            u64 b0 = dup2(bv.x), b1 = dup2(bv.y), b2 = dup2(bv.z), b3 = dup2(bv.w);
            fma2(acc[0][0], a01, b0); fma2(acc[1][0], a23, b0);
            fma2(acc[0][1], a01, b1); fma2(acc[1][1], a23, b1);
            fma2(acc[0][2], a01, b2); fma2(acc[1][2], a23, b2);
            fma2(acc[0][3], a01, b3); fma2(acc[1][3], a23, b3);
        }
    }

    float bn[4];
    #pragma unroll
    for (int j = 0; j < 4; j++) {
        int n = n0 + tx*4 + j;
        float v = 0.f;
        if (bias1) v += bias1[n];
        if (bias2) v += bias2[n];
        bn[j] = v;
    }
    float* Cb = C + z * bsC;
    #pragma unroll
    for (int p = 0; p < 2; p++) {
        long mr = m0 + ty*4 + 2*p;
        float4 r0, r1;
        r0.x = lo32(acc[p][0]) + bn[0]; r1.x = hi32(acc[p][0]) + bn[0];
        r0.y = lo32(acc[p][1]) + bn[1]; r1.y = hi32(acc[p][1]) + bn[1];
        r0.z = lo32(acc[p][2]) + bn[2]; r1.z = hi32(acc[p][2]) + bn[2];
        r0.w = lo32(acc[p][3]) + bn[3]; r1.w = hi32(acc[p][3]) + bn[3];
        *(float4*)&Cb[mr * ldc + n0 + tx*4]     = r0;
        *(float4*)&Cb[(mr+1) * ldc + n0 + tx*4] = r1;
    }
}

// ---------------- fused LSTM step: gates GEMM + elementwise ------------------
// Block covers 32 batch rows x 16 d-columns, with all 4 gates (column remap
// jj = dd*4 + gate) so the elementwise stage is register-only.
__global__ void __launch_bounds__(128) lstm_step(
    const float* __restrict__ hprev, const float* __restrict__ cprev,
    const float* __restrict__ Whh,
    const float* __restrict__ X,      // X[b,4096] for this t (incl. biases)
    float* __restrict__ Hout, float* __restrict__ cnew,
    float* __restrict__ outp)         // out[t] base: [b,3072]
{
    __shared__ float At[16][36];
    __shared__ float Bt[16][68];
    const int tid = threadIdx.x;
    const int tx = tid & 15, ty = tid >> 4;   // ty 0..7
    const int dtile = blockIdx.x;             // 0..63 (16 d each)
    const int m0 = blockIdx.y * 32;

    const int arow = tid >> 2, akq = tid & 3; // arow 0..31
    const float* Arow = hprev + (long)(m0 + arow) * 1024 + akq * 4;

    int jj0 = tid >> 2,          kq0 = tid & 3;
    int jj1 = (tid + 128) >> 2,  kq1 = tid & 3;
    const float* Brow0;
    const float* Brow1;
    {
        int gate = jj0 & 3, dd = jj0 >> 2;
        Brow0 = Whh + (long)(gate*1024 + dtile*16 + dd) * 1024 + kq0*4;
        gate = jj1 & 3; dd = jj1 >> 2;
        Brow1 = Whh + (long)(gate*1024 + dtile*16 + dd) * 1024 + kq1*4;
    }

    u64 acc[2][4];
    #pragma unroll
    for (int p = 0; p < 2; p++)
        #pragma unroll
        for (int j = 0; j < 4; j++) acc[p][j] = 0ull;

    float4 ra  = *(const float4*)Arow;
    float4 rb0 = *(const float4*)Brow0;
    float4 rb1 = *(const float4*)Brow1;

    for (int k0 = 0; k0 < 1024; k0 += 16) {
        __syncthreads();
        At[akq*4+0][arow] = ra.x;
        At[akq*4+1][arow] = ra.y;
        At[akq*4+2][arow] = ra.z;
        At[akq*4+3][arow] = ra.w;
        Bt[kq0*4+0][jj0] = rb0.x;
        Bt[kq0*4+1][jj0] = rb0.y;
        Bt[kq0*4+2][jj0] = rb0.z;
        Bt[kq0*4+3][jj0] = rb0.w;
        Bt[kq1*4+0][jj1] = rb1.x;
        Bt[kq1*4+1][jj1] = rb1.y;
        Bt[kq1*4+2][jj1] = rb1.z;
        Bt[kq1*4+3][jj1] = rb1.w;
        __syncthreads();
        if (k0 + 16 < 1024) {
            ra  = *(const float4*)(Arow  + k0 + 16);
            rb0 = *(const float4*)(Brow0 + k0 + 16);
            rb1 = *(const float4*)(Brow1 + k0 + 16);
        }
        #pragma unroll
        for (int k = 0; k < 16; k++) {
            u64 a01 = *(const u64*)&At[k][ty*4];
            u64 a23 = *(const u64*)&At[k][ty*4+2];
            float4 bv = *(const float4*)&Bt[k][tx*4];
            u64 b0 = dup2(bv.x), b1 = dup2(bv.y), b2 = dup2(bv.z), b3 = dup2(bv.w);
            fma2(acc[0][0], a01, b0); fma2(acc[1][0], a23, b0);
            fma2(acc[0][1], a01, b1); fma2(acc[1][1], a23, b1);
            fma2(acc[0][2], a01, b2); fma2(acc[1][2], a23, b2);
            fma2(acc[0][3], a01, b3); fma2(acc[1][3], a23, b3);
        }
    }

    // acc[p][j]: j = gate (i,f,g,o), column d = dtile*16 + tx,
    // packed pair = batch rows (m0+ty*4+2p, +1).
    const int d = dtile*16 + tx;
    #pragma unroll
    for (int p = 0; p < 2; p++) {
        #pragma unroll
        for (int h = 0; h < 2; h++) {
            int bg = m0 + ty*4 + 2*p + h;
            float iv = h ? hi32(acc[p][0]) : lo32(acc[p][0]);
            float fv = h ? hi32(acc[p][1]) : lo32(acc[p][1]);
            float gv = h ? hi32(acc[p][2]) : lo32(acc[p][2]);
            float ov = h ? hi32(acc[p][3]) : lo32(acc[p][3]);
            const float* Xr = X + (long)bg * 4096;
            iv += Xr[d]; fv += Xr[1024+d]; gv += Xr[2048+d]; ov += Xr[3072+d];
            float co = cprev[bg*1024 + d];
            float si = 1.f/(1.f + expf(-iv));
            float sf = 1.f/(1.f + expf(-fv));
            float so = 1.f/(1.f + expf(-ov));
            float cn = sf*co + si*tanhf(gv);
            float hn = so*tanhf(cn);
            cnew[bg*1024 + d] = cn;
            Hout[bg*1024 + d] = hn;
            outp[(long)bg*3072 + d] = hn;
        }
    }
}

// ---------------- encoder online-softmax scan over t (per (b,n)) ------------
__global__ void __launch_bounds__(256) enc_scan(float* __restrict__ E)
{
    int gid = blockIdx.x * 256 + threadIdx.x;   // 0..32767
    int b = gid >> 9, n = gid & 511;
    float m = -1e30f, s = 0.f;
    float* base = E + (long)b * (64*512) + n;
    for (int t = 0; t < 64; t++) {
        float e  = base[t*512];
        float m2 = fmaxf(m, e);
        s = s * expf(m - m2) + expf(e - m2);
        float sc = (t == 0) ? e : expf(e - m2) / s;
        base[t*512] = sc;
        m = m2;
    }
}

// ---------------- row softmax over n=512, in place ---------------------------
__global__ void __launch_bounds__(256) softmax512(float* __restrict__ E)
{
    __shared__ float red[8];
    __shared__ float fin;
    long row = blockIdx.x;
    float* p = E + row * 512;
    int tid = threadIdx.x;
    int lane = tid & 31, wid = tid >> 5;
    float x0 = p[tid], x1 = p[tid + 256];
    float m = fmaxf(x0, x1);
    #pragma unroll
    for (int o = 16; o; o >>= 1) m = fmaxf(m, __shfl_xor_sync(0xffffffffu, m, o));
    if (lane == 0) red[wid] = m;
    __syncthreads();
    if (tid < 32) {
        float v = (lane < 8) ? red[lane] : -1e30f;
        #pragma unroll
        for (int o = 4; o; o >>= 1) v = fmaxf(v, __shfl_xor_sync(0xffffffffu, v, o));
        if (lane == 0) fin = v;
    }
    __syncthreads();
    float M = fin;
    float e0 = expf(x0 - M), e1 = expf(x1 - M);
    float s = e0 + e1;
    #pragma unroll
    for (int o = 16; o; o >>= 1) s += __shfl_xor_sync(0xffffffffu, s, o);
    if (lane == 0) red[wid] = s;
    __syncthreads();
    if (tid < 32) {
        float v = (lane < 8) ? red[lane] : 0.f;
        #pragma unroll
        for (int o = 4; o; o >>= 1) v += __shfl_xor_sync(0xffffffffu, v, o);
        if (lane == 0) fin = v;
    }
    __syncthreads();
    float inv = 1.f / fin;
    p[tid]       = e0 * inv;
    p[tid + 256] = e1 * inv;
}

// ---------------- causal decoder softmax over tp (row len 64), in place ------
__global__ void __launch_bounds__(64) softmax_dec(float* __restrict__ ED)
{
    __shared__ float red[2];
    int row = blockIdx.x;        // b*64 + t
    int t = row & 63;
    int tid = threadIdx.x;       // tp
    float* p = ED + (long)row * 64;
    if (t == 0) { p[tid] = 0.f; return; }   // cd forced to zero at t==0
    float x = (tid < t) ? p[tid] : -1e30f;
    int lane = tid & 31, wid = tid >> 5;
    float m = x;
    #pragma unroll
    for (int o = 16; o; o >>= 1) m = fmaxf(m, __shfl_xor_sync(0xffffffffu, m, o));
    if (lane == 0) red[wid] = m;
    __syncthreads();
    float M = fmaxf(red[0], red[1]);
    float e = expf(x - M);                  // underflows to 0 for masked tp
    float s = e;
    #pragma unroll
    for (int o = 16; o; o >>= 1) s += __shfl_xor_sync(0xffffffffu, s, o);
    __syncthreads();
    if (lane == 0) red[wid] = s;
    __syncthreads();
    float S = red[0] + red[1];
    p[tid] = e / S;
}

// ---------------- host driver ------------------------------------------------
extern "C" void kernel_launch(void* const* d_in, const int* in_sizes, int n_in,
                              void* d_out, int out_size)
{
    (void)in_sizes; (void)n_in; (void)out_size;
    const int*   tok   = (const int*)  d_in[0];
    const float* h_e   = (const float*)d_in[1];
    const float* h0    = (const float*)d_in[2];
    const float* c0    = (const float*)d_in[3];
    const float* W_emb = (const float*)d_in[4];
    const float* W_ih  = (const float*)d_in[5];
    const float* W_hh  = (const float*)d_in[6];
    const float* b_ih  = (const float*)d_in[7];
    const float* b_hh  = (const float*)d_in[8];
    const float* W_enc = (const float*)d_in[9];
    const float* b_enc = (const float*)d_in[10];
    const float* W_dec = (const float*)d_in[11];
    const float* b_dec = (const float*)d_in[12];
    float* out = (float*)d_out;

    float *X, *H, *Q, *QD, *E, *ED, *c;
    cudaGetSymbolAddress((void**)&X,  g_X);
    cudaGetSymbolAddress((void**)&H,  g_H);
    cudaGetSymbolAddress((void**)&Q,  g_Q);
    cudaGetSymbolAddress((void**)&QD, g_QD);
    cudaGetSymbolAddress((void**)&E,  g_E);
    cudaGetSymbolAddress((void**)&ED, g_ED);
    cudaGetSymbolAddress((void**)&c,  g_c);

    // 1) X[t,b,:] = W_emb[tok] @ W_ih^T + b_ih + b_hh    (M=4096,N=4096,K=512)
    gemm64<true,false><<<dim3(64,64,1),256>>>(W_emb,512,tok, W_ih,512,
                                              X,4096, 512, b_ih,b_hh, 0,0,0);

    // 2) sequential LSTM, fused gates GEMM + elementwise; writes H[t] and out h-slice
    for (int t = 0; t < 64; t++) {
        lstm_step<<<dim3(64,2,1),128>>>(
            t ? H + (long)(t-1)*65536 : h0,
            t ? c : c0,
            W_hh,
            X + (long)t*262144,
            H + (long)t*65536, c,
            out + (long)t*196608);
    }

    // 3) Q = H@W_enc^T + b_enc ; QD = H@W_dec^T + b_dec   (M=4096,N=1024,K=1024)
    gemm64<false,false><<<dim3(16,64,1),256>>>(H,1024,nullptr, W_enc,1024,
                                               Q,1024, 1024, b_enc,nullptr, 0,0,0);
    gemm64<false,false><<<dim3(16,64,1),256>>>(H,1024,nullptr, W_dec,1024,
                                               QD,1024, 1024, b_dec,nullptr, 0,0,0);

    // 4) E[b][t][n] = Q[t,b,:] . h_e[n,b,:]   (per-b NT, M=64,N=512,K=1024)
    gemm64<false,false><<<dim3(8,1,64),256>>>(Q,65536,nullptr, h_e,65536,
                                              E,512, 1024, nullptr,nullptr,
                                              1024,1024,32768);
    // 5) online-softmax scan over t, then row softmax over n (both in place)
    enc_scan<<<128,256>>>(E);
    softmax512<<<4096,256>>>(E);
    // 6) c_e = alpha_e @ h_e  -> out[..., 1024:2048]  (per-b NN, M=64,N=1024,K=512)
    gemm64<false,true><<<dim3(16,1,64),256>>>(E,512,nullptr, h_e,65536,
                                              out+1024,196608, 512, nullptr,nullptr,
                                              32768,1024,3072);

    // 7) ED[b][t][tp] = QD[t,b,:] . H[tp,b,:]   (per-b NT, M=64,N=64,K=1024)
    gemm64<false,false><<<dim3(1,1,64),256>>>(QD,65536,nullptr, H,65536,
                                              ED,64, 1024, nullptr,nullptr,
                                              1024,1024,4096);
    // 8) strictly-causal softmax (zeros at t==0)
    softmax_dec<<<4096,64>>>(ED);
    // 9) cd = alpha_d @ H -> out[..., 2048:3072]  (per-b NN, M=64,N=1024,K=64)
    gemm64<false,true><<<dim3(16,1,64),256>>>(ED,64,nullptr, H,65536,
                                              out+2048,196608, 64, nullptr,nullptr,
                                              4096,1024,3072);
}

// round 6
// speedup vs baseline: 1.5023x; 1.5023x over previous
#include <cuda_runtime.h>

typedef unsigned long long u64;
typedef unsigned int u32;

#define TT   64
#define BSS  64
#define DIMM 1024
#define G4   4096
#define SRCN 512

// ---------------- scratch (static device globals; no runtime alloc) ----------
__device__ float g_X [TT*BSS*G4];     // 64 MB: pre-activations X[t,b,4096]
__device__ float g_H [TT*BSS*DIMM];   // 16 MB: hidden history H[t,b,1024]
__device__ float g_Q [TT*BSS*DIMM];   // 16 MB: encoder queries
__device__ float g_QD[TT*BSS*DIMM];   // 16 MB: decoder queries
__device__ float g_E [BSS*TT*SRCN];   //  8 MB: enc scores -> sc -> alpha (in place)
__device__ float g_ED[BSS*TT*TT];     //  1 MB: dec scores -> alpha (in place)
__device__ float g_c [BSS*DIMM];      // cell state
__device__ float g_P [4*BSS*G4];      //  4 MB: K-split partial gate sums

// ---------------- f32x2 packed helpers --------------------------------------
__device__ __forceinline__ void fma2(u64& a, u64 x, u64 y){
    asm("fma.rn.f32x2 %0, %1, %2, %0;" : "+l"(a) : "l"(x), "l"(y));
}
__device__ __forceinline__ u64 dup2(float f){
    u32 u = __float_as_uint(f);
    u64 r; asm("mov.b64 %0, {%1, %1};" : "=l"(r) : "r"(u));
    return r;
}
__device__ __forceinline__ float lo32(u64 v){ return __uint_as_float((u32)v); }
__device__ __forceinline__ float hi32(u64 v){ return __uint_as_float((u32)(v>>32)); }

// ---------------- generic 64x64 NT/NN GEMM, C[m,n] = sum_k A[m,k]*B[.,k] ----
template<bool GATHER, bool BNN>
__global__ void __launch_bounds__(256) gemm64(
    const float* __restrict__ A, long lda, const int* __restrict__ ridx,
    const float* __restrict__ B, long ldb,
    float* __restrict__ C, long ldc, int K,
    const float* __restrict__ bias1, const float* __restrict__ bias2,
    long bsA, long bsB, long bsC)
{
    __shared__ float At[16][68];
    __shared__ float Bt[16][68];
    const int tid = threadIdx.x;
    const int tx = tid & 15, ty = tid >> 4;
    const int m0 = blockIdx.y * 64;
    const int n0 = blockIdx.x * 64;
    const long z = blockIdx.z;

    const int arow = tid >> 2, akq = tid & 3;
    const float* Arow;
    {
        const float* Ab = A + z * bsA;
        long mrow = m0 + arow;
        if (GATHER) mrow = ridx[mrow];
        Arow = Ab + mrow * lda + akq * 4;
    }
    const float* Brow;
    int bk = 0, bnq = 0, brow = 0, bkq = 0;
    {
        const float* Bb = B + z * bsB;
        if (BNN) { bk = tid >> 4; bnq = tid & 15; Brow = Bb + (long)bk * ldb + n0 + bnq * 4; }
        else     { brow = tid >> 2; bkq = tid & 3; Brow = Bb + (long)(n0 + brow) * ldb + bkq * 4; }
    }

    u64 acc[2][4];
    #pragma unroll
    for (int p = 0; p < 2; p++)
        #pragma unroll
        for (int j = 0; j < 4; j++) acc[p][j] = 0ull;

    float4 ra = *(const float4*)(Arow);
    float4 rb = *(const float4*)(Brow);

    for (int k0 = 0; k0 < K; k0 += 16) {
        __syncthreads();
        At[akq*4+0][arow] = ra.x;
        At[akq*4+1][arow] = ra.y;
        At[akq*4+2][arow] = ra.z;
        At[akq*4+3][arow] = ra.w;
        if (BNN) {
            *(float4*)&Bt[bk][bnq*4] = rb;
        } else {
            Bt[bkq*4+0][brow] = rb.x;
            Bt[bkq*4+1][brow] = rb.y;
            Bt[bkq*4+2][brow] = rb.z;
            Bt[bkq*4+3][brow] = rb.w;
        }
        __syncthreads();
        if (k0 + 16 < K) {
            ra = *(const float4*)(Arow + k0 + 16);
            rb = BNN ? *(const float4*)(Brow + (long)(k0 + 16) * ldb)
                     : *(const float4*)(Brow + k0 + 16);
        }
        #pragma unroll
        for (int k = 0; k < 16; k++) {
            u64 a01 = *(const u64*)&At[k][ty*4];
            u64 a23 = *(const u64*)&At[k][ty*4+2];
            float4 bv = *(const float4*)&Bt[k][tx*4];
            u64 b0 = dup2(bv.x), b1 = dup2(bv.y), b2 = dup2(bv.z), b3 = dup2(bv.w);
            fma2(acc[0][0], a01, b0); fma2(acc[1][0], a23, b0);
            fma2(acc[0][1], a01, b1); fma2(acc[1][1], a23, b1);
            fma2(acc[0][2], a01, b2); fma2(acc[1][2], a23, b2);
            fma2(acc[0][3], a01, b3); fma2(acc[1][3], a23, b3);
        }
    }

    float bn[4];
    #pragma unroll
    for (int j = 0; j < 4; j++) {
        int n = n0 + tx*4 + j;
        float v = 0.f;
        if (bias1) v += bias1[n];
        if (bias2) v += bias2[n];
        bn[j] = v;
    }
    float* Cb = C + z * bsC;
    #pragma unroll
    for (int p = 0; p < 2; p++) {
        long mr = m0 + ty*4 + 2*p;
        float4 r0, r1;
        r0.x = lo32(acc[p][0]) + bn[0]; r1.x = hi32(acc[p][0]) + bn[0];
        r0.y = lo32(acc[p][1]) + bn[1]; r1.y = hi32(acc[p][1]) + bn[1];
        r0.z = lo32(acc[p][2]) + bn[2]; r1.z = hi32(acc[p][2]) + bn[2];
        r0.w = lo32(acc[p][3]) + bn[3]; r1.w = hi32(acc[p][3]) + bn[3];
        *(float4*)&Cb[mr * ldc + n0 + tx*4]     = r0;
        *(float4*)&Cb[(mr+1) * ldc + n0 + tx*4] = r1;
    }
}

// ---------------- LSTM step, stage 1: K-split gates GEMM ---------------------
// grid (64 n-tiles, 2 m-halves, 4 K-chunks), 128 threads.
// P[ks][b][jj] partial of h_prev @ W_hh^T over K-chunk ks.
__global__ void __launch_bounds__(128) lstm_gemm(
    const float* __restrict__ hprev, const float* __restrict__ Whh,
    float* __restrict__ P)
{
    __shared__ float At[16][36];
    __shared__ float Bt[16][68];
    const int tid = threadIdx.x;
    const int tx = tid & 15, ty = tid >> 4;   // ty 0..7
    const int n0 = blockIdx.x * 64;
    const int m0 = blockIdx.y * 32;
    const int kbase = blockIdx.z * 256;

    const int arow = tid >> 2, akq = tid & 3; // arow 0..31
    const float* Arow = hprev + (long)(m0 + arow) * 1024 + kbase + akq * 4;
    const int brow = tid >> 2, bkq = tid & 3;
    const float* Brow0 = Whh + (long)(n0 + brow)      * 1024 + kbase + bkq * 4;
    const float* Brow1 = Whh + (long)(n0 + brow + 32) * 1024 + kbase + bkq * 4;

    u64 acc[2][4];
    #pragma unroll
    for (int p = 0; p < 2; p++)
        #pragma unroll
        for (int j = 0; j < 4; j++) acc[p][j] = 0ull;

    float4 ra  = *(const float4*)Arow;
    float4 rb0 = *(const float4*)Brow0;
    float4 rb1 = *(const float4*)Brow1;

    for (int k0 = 0; k0 < 256; k0 += 16) {
        __syncthreads();
        At[akq*4+0][arow] = ra.x;
        At[akq*4+1][arow] = ra.y;
        At[akq*4+2][arow] = ra.z;
        At[akq*4+3][arow] = ra.w;
        Bt[bkq*4+0][brow] = rb0.x;
        Bt[bkq*4+1][brow] = rb0.y;
        Bt[bkq*4+2][brow] = rb0.z;
        Bt[bkq*4+3][brow] = rb0.w;
        Bt[bkq*4+0][brow+32] = rb1.x;
        Bt[bkq*4+1][brow+32] = rb1.y;
        Bt[bkq*4+2][brow+32] = rb1.z;
        Bt[bkq*4+3][brow+32] = rb1.w;
        __syncthreads();
        if (k0 + 16 < 256) {
            ra  = *(const float4*)(Arow  + k0 + 16);
            rb0 = *(const float4*)(Brow0 + k0 + 16);
            rb1 = *(const float4*)(Brow1 + k0 + 16);
        }
        #pragma unroll
        for (int k = 0; k < 16; k++) {
            u64 a01 = *(const u64*)&At[k][ty*4];
            u64 a23 = *(const u64*)&At[k][ty*4+2];
            float4 bv = *(const float4*)&Bt[k][tx*4];
            u64 b0 = dup2(bv.x), b1 = dup2(bv.y), b2 = dup2(bv.z), b3 = dup2(bv.w);
            fma2(acc[0][0], a01, b0); fma2(acc[1][0], a23, b0);
            fma2(acc[0][1], a01, b1); fma2(acc[1][1], a23, b1);
            fma2(acc[0][2], a01, b2); fma2(acc[1][2], a23, b2);
            fma2(acc[0][3], a01, b3); fma2(acc[1][3], a23, b3);
        }
    }

    float* Pb = P + (long)blockIdx.z * (64 * 4096);
    #pragma unroll
    for (int p = 0; p < 2; p++) {
        long mr = m0 + ty*4 + 2*p;
        float4 r0, r1;
        r0.x = lo32(acc[p][0]); r1.x = hi32(acc[p][0]);
        r0.y = lo32(acc[p][1]); r1.y = hi32(acc[p][1]);
        r0.z = lo32(acc[p][2]); r1.z = hi32(acc[p][2]);
        r0.w = lo32(acc[p][3]); r1.w = hi32(acc[p][3]);
        *(float4*)&Pb[mr * 4096 + n0 + tx*4]     = r0;
        *(float4*)&Pb[(mr+1) * 4096 + n0 + tx*4] = r1;
    }
}

// ---------------- LSTM step, stage 2: reduce partials + elementwise ----------
__global__ void __launch_bounds__(128) lstm_fin(
    const float* __restrict__ P, const float* __restrict__ X,
    const float* __restrict__ cprev,
    float* __restrict__ cnew, float* __restrict__ Hout,
    float* __restrict__ outp)
{
    int idx = blockIdx.x * 128 + threadIdx.x;   // 0..16383
    int b  = idx >> 8;                          // 64
    int dq = (idx & 255) * 4;                   // d base (float4)

    float4 g[4];
    #pragma unroll
    for (int gate = 0; gate < 4; gate++) {
        long off = (long)b * 4096 + gate * 1024 + dq;
        float4 v = *(const float4*)&X[off];
        #pragma unroll
        for (int ks = 0; ks < 4; ks++) {
            float4 p = *(const float4*)&P[(long)ks * (64*4096) + off];
            v.x += p.x; v.y += p.y; v.z += p.z; v.w += p.w;
        }
        g[gate] = v;
    }
    float4 co = *(const float4*)&cprev[b*1024 + dq];
    float4 cn, hn;
    #pragma unroll
    for (int j = 0; j < 4; j++) {
        float iv = (&g[0].x)[j], fv = (&g[1].x)[j], gv = (&g[2].x)[j], ov = (&g[3].x)[j];
        float c_old = (&co.x)[j];
        float si = 1.f / (1.f + __expf(-iv));
        float sf = 1.f / (1.f + __expf(-fv));
        float so = 1.f / (1.f + __expf(-ov));
        float cc = sf * c_old + si * tanhf(gv);
        (&cn.x)[j] = cc;
        (&hn.x)[j] = so * tanhf(cc);
    }
    *(float4*)&cnew[b*1024 + dq] = cn;
    *(float4*)&Hout[b*1024 + dq] = hn;
    *(float4*)&outp[(long)b*3072 + dq] = hn;
}

// ---------------- encoder online-softmax scan over t (per (b,n)) ------------
__global__ void __launch_bounds__(256) enc_scan(float* __restrict__ E)
{
    int gid = blockIdx.x * 256 + threadIdx.x;   // 0..32767
    int b = gid >> 9, n = gid & 511;
    float m = -1e30f, s = 0.f;
    float* base = E + (long)b * (64*512) + n;
    for (int t = 0; t < 64; t++) {
        float e  = base[t*512];
        float m2 = fmaxf(m, e);
        s = s * __expf(m - m2) + __expf(e - m2);
        float sc = (t == 0) ? e : __expf(e - m2) / s;
        base[t*512] = sc;
        m = m2;
    }
}

// ---------------- row softmax over n=512, in place ---------------------------
__global__ void __launch_bounds__(256) softmax512(float* __restrict__ E)
{
    __shared__ float red[8];
    __shared__ float fin;
    long row = blockIdx.x;
    float* p = E + row * 512;
    int tid = threadIdx.x;
    int lane = tid & 31, wid = tid >> 5;
    float x0 = p[tid], x1 = p[tid + 256];
    float m = fmaxf(x0, x1);
    #pragma unroll
    for (int o = 16; o; o >>= 1) m = fmaxf(m, __shfl_xor_sync(0xffffffffu, m, o));
    if (lane == 0) red[wid] = m;
    __syncthreads();
    if (tid < 32) {
        float v = (lane < 8) ? red[lane] : -1e30f;
        #pragma unroll
        for (int o = 4; o; o >>= 1) v = fmaxf(v, __shfl_xor_sync(0xffffffffu, v, o));
        if (lane == 0) fin = v;
    }
    __syncthreads();
    float M = fin;
    float e0 = __expf(x0 - M), e1 = __expf(x1 - M);
    float s = e0 + e1;
    #pragma unroll
    for (int o = 16; o; o >>= 1) s += __shfl_xor_sync(0xffffffffu, s, o);
    if (lane == 0) red[wid] = s;
    __syncthreads();
    if (tid < 32) {
        float v = (lane < 8) ? red[lane] : 0.f;
        #pragma unroll
        for (int o = 4; o; o >>= 1) v += __shfl_xor_sync(0xffffffffu, v, o);
        if (lane == 0) fin = v;
    }
    __syncthreads();
    float inv = 1.f / fin;
    p[tid]       = e0 * inv;
    p[tid + 256] = e1 * inv;
}

// ---------------- causal decoder softmax over tp (row len 64), in place ------
__global__ void __launch_bounds__(64) softmax_dec(float* __restrict__ ED)
{
    __shared__ float red[2];
    int row = blockIdx.x;        // b*64 + t
    int t = row & 63;
    int tid = threadIdx.x;       // tp
    float* p = ED + (long)row * 64;
    if (t == 0) { p[tid] = 0.f; return; }   // cd forced to zero at t==0
    float x = (tid < t) ? p[tid] : -1e30f;
    int lane = tid & 31, wid = tid >> 5;
    float m = x;
    #pragma unroll
    for (int o = 16; o; o >>= 1) m = fmaxf(m, __shfl_xor_sync(0xffffffffu, m, o));
    if (lane == 0) red[wid] = m;
    __syncthreads();
    float M = fmaxf(red[0], red[1]);
    float e = __expf(x - M);
    float s = e;
    #pragma unroll
    for (int o = 16; o; o >>= 1) s += __shfl_xor_sync(0xffffffffu, s, o);
    __syncthreads();
    if (lane == 0) red[wid] = s;
    __syncthreads();
    float S = red[0] + red[1];
    p[tid] = e / S;
}

// ---------------- host driver ------------------------------------------------
extern "C" void kernel_launch(void* const* d_in, const int* in_sizes, int n_in,
                              void* d_out, int out_size)
{
    (void)in_sizes; (void)n_in; (void)out_size;
    const int*   tok   = (const int*)  d_in[0];
    const float* h_e   = (const float*)d_in[1];
    const float* h0    = (const float*)d_in[2];
    const float* c0    = (const float*)d_in[3];
    const float* W_emb = (const float*)d_in[4];
    const float* W_ih  = (const float*)d_in[5];
    const float* W_hh  = (const float*)d_in[6];
    const float* b_ih  = (const float*)d_in[7];
    const float* b_hh  = (const float*)d_in[8];
    const float* W_enc = (const float*)d_in[9];
    const float* b_enc = (const float*)d_in[10];
    const float* W_dec = (const float*)d_in[11];
    const float* b_dec = (const float*)d_in[12];
    float* out = (float*)d_out;

    float *X, *H, *Q, *QD, *E, *ED, *c, *P;
    cudaGetSymbolAddress((void**)&X,  g_X);
    cudaGetSymbolAddress((void**)&H,  g_H);
    cudaGetSymbolAddress((void**)&Q,  g_Q);
    cudaGetSymbolAddress((void**)&QD, g_QD);
    cudaGetSymbolAddress((void**)&E,  g_E);
    cudaGetSymbolAddress((void**)&ED, g_ED);
    cudaGetSymbolAddress((void**)&c,  g_c);
    cudaGetSymbolAddress((void**)&P,  g_P);

    // 1) X[t,b,:] = W_emb[tok] @ W_ih^T + b_ih + b_hh    (M=4096,N=4096,K=512)
    gemm64<true,false><<<dim3(64,64,1),256>>>(W_emb,512,tok, W_ih,512,
                                              X,4096, 512, b_ih,b_hh, 0,0,0);

    // 2) sequential LSTM: K-split gates GEMM + reduce/elementwise
    for (int t = 0; t < 64; t++) {
        const float* hprev = t ? H + (long)(t-1)*65536 : h0;
        const float* cprev = t ? c : c0;
        lstm_gemm<<<dim3(64,2,4),128>>>(hprev, W_hh, P);
        lstm_fin<<<128,128>>>(P, X + (long)t*262144, cprev,
                              c, H + (long)t*65536, out + (long)t*196608);
    }

    // 3) Q = H@W_enc^T + b_enc ; QD = H@W_dec^T + b_dec   (M=4096,N=1024,K=1024)
    gemm64<false,false><<<dim3(16,64,1),256>>>(H,1024,nullptr, W_enc,1024,
                                               Q,1024, 1024, b_enc,nullptr, 0,0,0);
    gemm64<false,false><<<dim3(16,64,1),256>>>(H,1024,nullptr, W_dec,1024,
                                               QD,1024, 1024, b_dec,nullptr, 0,0,0);

    // 4) E[b][t][n] = Q[t,b,:] . h_e[n,b,:]   (per-b NT, M=64,N=512,K=1024)
    gemm64<false,false><<<dim3(8,1,64),256>>>(Q,65536,nullptr, h_e,65536,
                                              E,512, 1024, nullptr,nullptr,
                                              1024,1024,32768);
    // 5) online-softmax scan over t, then row softmax over n (both in place)
    enc_scan<<<128,256>>>(E);
    softmax512<<<4096,256>>>(E);
    // 6) c_e = alpha_e @ h_e  -> out[..., 1024:2048]  (per-b NN, M=64,N=1024,K=512)
    gemm64<false,true><<<dim3(16,1,64),256>>>(E,512,nullptr, h_e,65536,
                                              out+1024,196608, 512, nullptr,nullptr,
                                              32768,1024,3072);

    // 7) ED[b][t][tp] = QD[t,b,:] . H[tp,b,:]   (per-b NT, M=64,N=64,K=1024)
    gemm64<false,false><<<dim3(1,1,64),256>>>(QD,65536,nullptr, H,65536,
                                              ED,64, 1024, nullptr,nullptr,
                                              1024,1024,4096);
    // 8) strictly-causal softmax (zeros at t==0)
    softmax_dec<<<4096,64>>>(ED);
    // 9) cd = alpha_d @ H -> out[..., 2048:3072]  (per-b NN, M=64,N=1024,K=64)
    gemm64<false,true><<<dim3(16,1,64),256>>>(ED,64,nullptr, H,65536,
                                              out+2048,196608, 64, nullptr,nullptr,
                                              4096,1024,3072);
}